// round 7
// baseline (speedup 1.0000x reference)
#include <cuda_runtime.h>
#include <cstdint>

#define NSTATES 35
#define NB      64
#define TT      512
#define DDIM    2496
#define BTROWS  (NB * TT)   // 32768
#define ROWW    128         // [w: 8 slots x 8 | kappa: 8 slots x 8] per (b,t)
#define KC      64          // fp32 elems per k-chunk
#define NCH     39          // 2496/64

// Scratch (no cudaMalloc). +16 pad rows (zero-init) so k_fwd never branches.
__device__ float g_w[(size_t)(BTROWS + 16) * ROWW];
__device__ float g_wsum[BTROWS + 16];
__device__ float g_xsqp[NB][16];

// ---------------------------------------------------------------------------
// helpers
// ---------------------------------------------------------------------------
__device__ __forceinline__ uint32_t smem_u32(const void* p) {
    return (uint32_t)__cvta_generic_to_shared(p);
}
__device__ __forceinline__ uint32_t cvt_bf2(float lo, float hi) {
    uint32_t r;
    asm("cvt.rn.bf16x2.f32 %0, %1, %2;" : "=r"(r) : "f"(hi), "f"(lo));
    return r;
}
__device__ __forceinline__ void mma_bf16(float* d,
    uint32_t a0, uint32_t a1, uint32_t a2, uint32_t a3, uint32_t b0, uint32_t b1) {
    asm volatile(
        "mma.sync.aligned.m16n8k16.row.col.f32.bf16.bf16.f32 "
        "{%0,%1,%2,%3}, {%4,%5,%6,%7}, {%8,%9}, {%0,%1,%2,%3};\n"
        : "+f"(d[0]), "+f"(d[1]), "+f"(d[2]), "+f"(d[3])
        : "r"(a0), "r"(a1), "r"(a2), "r"(a3), "r"(b0), "r"(b1));
}
__device__ __forceinline__ void ldsm4(uint32_t* r, uint32_t a) {
    asm volatile("ldmatrix.sync.aligned.m8n8.x4.shared.b16 {%0,%1,%2,%3}, [%4];"
        : "=r"(r[0]), "=r"(r[1]), "=r"(r[2]), "=r"(r[3]) : "r"(a));
}
__device__ __forceinline__ void ldsm2(uint32_t* r, uint32_t a) {
    asm volatile("ldmatrix.sync.aligned.m8n8.x2.shared.b16 {%0,%1}, [%2];"
        : "=r"(r[0]), "=r"(r[1]) : "r"(a));
}
__device__ __forceinline__ void sts64(uint32_t addr, uint32_t a, uint32_t b) {
    asm volatile("st.shared.v2.b32 [%0], {%1,%2};" :: "r"(addr), "r"(a), "r"(b));
}
__device__ __forceinline__ float bfly_sum32(float v) {
    const unsigned FULL = 0xffffffffu;
    v += __shfl_xor_sync(FULL, v, 16);
    v += __shfl_xor_sync(FULL, v, 8);
    v += __shfl_xor_sync(FULL, v, 4);
    v += __shfl_xor_sync(FULL, v, 2);
    v += __shfl_xor_sync(FULL, v, 1);
    return v;
}
__device__ __forceinline__ float bfly_sum8(float v) {
    const unsigned FULL = 0xffffffffu;
    v += __shfl_xor_sync(FULL, v, 1, 8);
    v += __shfl_xor_sync(FULL, v, 2, 8);
    v += __shfl_xor_sync(FULL, v, 4, 8);
    return v;
}

// ---------------------------------------------------------------------------
// GEMM: smem-staged bf16 m16n8k16 (at DRAM floor). Epilogue writes the
// 8x5 lane-slot layout for k_fwd: per row 128 floats, slot j (j=0..6) holds
// w[5j..5j+4] at j*8, slot 7 duplicates slot 6; kappa analog at +64.
// ---------------------------------------------------------------------------
__global__ void __launch_bounds__(128) k_gemm(const float* __restrict__ x,
                                              const float* __restrict__ mM) {
    __shared__ __align__(16) unsigned char smraw[21504];  // A 16384 | B 5120
    __shared__ float msq[40];
    const int tid = threadIdx.x, wid = tid >> 5, lane = tid & 31;
    const int wstart = wid * 32;
    const int hhalf = lane >> 4;
    const int l4 = lane & 15;
    const int xl = lane & 7;
    const int rowBase = blockIdx.x * 128;
    const uint32_t smA = smem_u32(smraw);
    const uint32_t smB = smA + 16384;

    const uint32_t aAddr0 = smA + (uint32_t)(wstart + 0 * 16 + l4) * 128;
    const uint32_t aAddr1 = smA + (uint32_t)(wstart + 1 * 16 + l4) * 128;
    uint32_t bAddr[5];
#pragma unroll
    for (int nt = 0; nt < 5; nt++) bAddr[nt] = smB + (uint32_t)(nt * 8 + xl) * 128;
    const int hvA = hhalf;
    const int hvB = (lane >> 3) & 1;

    float acc[2][5][4];
#pragma unroll
    for (int mt = 0; mt < 2; mt++)
#pragma unroll
        for (int nt = 0; nt < 5; nt++)
#pragma unroll
            for (int i = 0; i < 4; i++) acc[mt][nt][i] = 0.f;

    float xa0 = 0.f, xa1 = 0.f, xa2 = 0.f, xa3 = 0.f;
    float bacc[5] = {0.f, 0.f, 0.f, 0.f, 0.f};
    float4 av[16], bvf[5];

#define LOADCHUNK(CH) do {                                                      \
    int kc0 = (CH) * KC;                                                        \
    _Pragma("unroll")                                                           \
    for (int i = 0; i < 16; i++) {                                              \
        int r = wstart + i * 2 + hhalf;                                         \
        av[i] = *(const float4*)(x + (size_t)(rowBase + r) * DDIM + kc0 + l4*4);\
    }                                                                           \
    _Pragma("unroll")                                                           \
    for (int k = 0; k < 5; k++) {                                               \
        int s = (wid + 4 * k) * 2 + hhalf;                                      \
        int ss = s < NSTATES ? s : NSTATES - 1;                                 \
        float4 t = *(const float4*)(mM + (size_t)ss * DDIM + kc0 + l4 * 4);     \
        if (s >= NSTATES) { t.x = 0.f; t.y = 0.f; t.z = 0.f; t.w = 0.f; }       \
        bvf[k] = t;                                                             \
    } } while (0)

#define CVTSTS() do {                                                           \
    _Pragma("unroll")                                                           \
    for (int i = 0; i < 16; i++) {                                              \
        int sr = wstart + i * 2 + hhalf;                                        \
        float4 v = av[i];                                                       \
        xa0 = fmaf(v.x, v.x, xa0); xa1 = fmaf(v.y, v.y, xa1);                   \
        xa2 = fmaf(v.z, v.z, xa2); xa3 = fmaf(v.w, v.w, xa3);                   \
        uint32_t lo = cvt_bf2(v.x, v.y), hi = cvt_bf2(v.z, v.w);                \
        uint32_t ad = smA + (uint32_t)sr * 128                                  \
                    + (uint32_t)((((l4 >> 1) ^ (sr & 7)) << 4) + ((l4 & 1) << 3)); \
        sts64(ad, lo, hi);                                                      \
    }                                                                           \
    _Pragma("unroll")                                                           \
    for (int k = 0; k < 5; k++) {                                               \
        int s = (wid + 4 * k) * 2 + hhalf;                                      \
        float4 v = bvf[k];                                                      \
        bacc[k] = fmaf(v.x, v.x, fmaf(v.y, v.y, fmaf(v.z, v.z,                  \
                  fmaf(v.w, v.w, bacc[k]))));                                   \
        uint32_t lo = cvt_bf2(v.x, v.y), hi = cvt_bf2(v.z, v.w);                \
        uint32_t ad = smB + (uint32_t)s * 128                                   \
                    + (uint32_t)((((l4 >> 1) ^ (s & 7)) << 4) + ((l4 & 1) << 3)); \
        sts64(ad, lo, hi);                                                      \
    } } while (0)

#define MMASEC() do {                                                           \
    _Pragma("unroll")                                                           \
    for (int kt = 0; kt < 4; kt++) {                                            \
        uint32_t A0[4], A1[4];                                                  \
        uint32_t offA = (uint32_t)(((kt * 2 + hvA) ^ xl) << 4);                 \
        ldsm4(A0, aAddr0 + offA);                                               \
        ldsm4(A1, aAddr1 + offA);                                               \
        uint32_t offB = (uint32_t)(((kt * 2 + hvB) ^ xl) << 4);                 \
        _Pragma("unroll")                                                       \
        for (int nt = 0; nt < 5; nt++) {                                        \
            uint32_t B[2];                                                      \
            ldsm2(B, bAddr[nt] + offB);                                         \
            mma_bf16(acc[0][nt], A0[0], A0[1], A0[2], A0[3], B[0], B[1]);       \
            mma_bf16(acc[1][nt], A1[0], A1[1], A1[2], A1[3], B[0], B[1]);       \
        }                                                                       \
    } } while (0)

    LOADCHUNK(0);
    CVTSTS();
    __syncthreads();

    for (int ch = 0; ch < NCH; ch++) {
        bool more = (ch + 1 < NCH);
        if (more) LOADCHUNK(ch + 1);
        MMASEC();
        __syncthreads();
        if (more) {
            CVTSTS();
            __syncthreads();
        }
    }

    // exact fp32 m_sq
#pragma unroll
    for (int k = 0; k < 5; k++) {
        float v = bacc[k];
        v += __shfl_xor_sync(0xffffffffu, v, 1);
        v += __shfl_xor_sync(0xffffffffu, v, 2);
        v += __shfl_xor_sync(0xffffffffu, v, 4);
        v += __shfl_xor_sync(0xffffffffu, v, 8);
        int s = (wid + 4 * k) * 2 + hhalf;
        if (l4 == 0) msq[s] = v;
    }
    __syncthreads();

    // w = exp((m_sq - 2*xm)/-500) -> smem staging [128][42]
    float* wsm = (float*)smraw;
    const int g = lane >> 2, c = lane & 3;
    const float NEG_INV = -1.0f / 500.0f;
#pragma unroll
    for (int mt = 0; mt < 2; mt++) {
#pragma unroll
        for (int h = 0; h < 2; h++) {
            int rl = wstart + mt * 16 + g + h * 8;
#pragma unroll
            for (int nt = 0; nt < 5; nt++) {
                int col = nt * 8 + 2 * c;
                float v0 = acc[mt][nt][2 * h + 0];
                float v1 = acc[mt][nt][2 * h + 1];
                float w0 = (col     < NSTATES) ? __expf((msq[col]     - 2.f * v0) * NEG_INV) : 0.f;
                float w1 = (col + 1 < NSTATES) ? __expf((msq[col + 1] - 2.f * v1) * NEG_INV) : 0.f;
                *(float2*)&wsm[rl * 42 + col] = make_float2(w0, w1);
            }
        }
    }
    __syncthreads();

    // per-thread row pass: Wt, kappa, write 8x5 slot layout
    {
        int rl = tid;
        float wv[40];
#pragma unroll
        for (int j = 0; j < 40; j++) wv[j] = wsm[rl * 42 + j];
        float Wt = 0.f;
#pragma unroll
        for (int j = 0; j < NSTATES; j++) Wt += wv[j];
        float kap[35];
#pragma unroll
        for (int j = 0; j < NSTATES; j++) {
            int j1 = (j + 1) % NSTATES, j2 = (j + 2) % NSTATES;
            kap[j] = fmaf(0.1f, wv[j], fmaf(0.8f, wv[j1], 0.08f * wv[j2]));
        }
        float* gr = g_w + (size_t)(rowBase + rl) * ROWW;
#pragma unroll
        for (int j = 0; j < 8; j++) {
            int bsl = 5 * (j < 7 ? j : 6);
            *(float4*)(gr + j * 8)     = make_float4(wv[bsl], wv[bsl+1], wv[bsl+2], wv[bsl+3]);
            *(float4*)(gr + j * 8 + 4) = make_float4(wv[bsl+4], 0.f, 0.f, 0.f);
            *(float4*)(gr + 64 + j * 8)     = make_float4(kap[bsl], kap[bsl+1], kap[bsl+2], kap[bsl+3]);
            *(float4*)(gr + 64 + j * 8 + 4) = make_float4(kap[bsl+4], 0.f, 0.f, 0.f);
        }
        g_wsum[rowBase + rl] = Wt;
    }

    float tot = bfly_sum32(xa0 + xa1 + xa2 + xa3);
    if (lane == 0)
        g_xsqp[(rowBase + wstart) >> 9][(blockIdx.x * 4 + wid) & 15] = tot;
}

// ---------------------------------------------------------------------------
// Forward recursion: 8 lanes x 5 states in registers. Lane j holds states
// 5j..5j+4 (j<=6); lane 7 duplicates lane 6 so shfl(src=j-1, width 8) gives
// the cyclic wrap for free (lane 7's prev is lane 5). Per step: 2 boundary
// shfl + 3-shfl width-8 butterfly (vs 11 shfl before). kappa-form keeps the
// scalar S chain 2 steps off the critical path.
// ---------------------------------------------------------------------------
__device__ __forceinline__ void fstep(float& p0, float& p1, float& p2,
                                      float& p3, float& p4,
                                      float& S, float& Rn,
                                      float4 wA, float wE,
                                      float4 kA, float kE,
                                      float Ws, int jprev, bool zmask) {
    const unsigned FULL = 0xffffffffu;
    const float EPS = 0.02f / 35.0f;
    float sigma = EPS * S;
    float b4 = __shfl_sync(FULL, p4, jprev, 8);
    float b3 = __shfl_sync(FULL, p3, jprev, 8);
    float s2 = fmaf(0.1f, p2, fmaf(0.8f, p1, 0.08f * p0));
    float s3 = fmaf(0.1f, p3, fmaf(0.8f, p2, 0.08f * p1));
    float s4 = fmaf(0.1f, p4, fmaf(0.8f, p3, 0.08f * p2));
    float s0 = fmaf(0.1f, p0, fmaf(0.8f, b4, 0.08f * b3));
    float s1 = fmaf(0.1f, p1, fmaf(0.8f, p0, 0.08f * b4));
    p0 = wA.x * (s0 + sigma);
    p1 = wA.y * (s1 + sigma);
    p2 = wA.z * (s2 + sigma);
    p3 = wA.w * (s3 + sigma);
    p4 = wE   * (s4 + sigma);
    // z for NEXT step's R: kappa of row t+1
    float za = fmaf(p0, kA.x, p1 * kA.y);
    float zb = fmaf(p2, kA.z, p3 * kA.w);
    float z = fmaf(p4, kE, za + zb);
    z = zmask ? z : 0.0f;
    z += __shfl_xor_sync(FULL, z, 1, 8);
    z += __shfl_xor_sync(FULL, z, 2, 8);
    z += __shfl_xor_sync(FULL, z, 4, 8);
    S = fmaf(sigma, Ws, Rn);       // S_t  (Rn = R_t from last step's bfly)
    Rn = z;                        // R_{t+1}
}

__global__ void __launch_bounds__(32) k_fwd(float* __restrict__ out) {
    const int b = blockIdx.x;
    const int lane = threadIdx.x & 31;
    const int j = lane & 7;
    const float* rb = g_w + (size_t)b * TT * ROWW;
    const float* wsb = g_wsum + b * TT;
    const float NEG_INV = -1.0f / 500.0f;
    const int jprev = (j == 0) ? 7 : ((j == 7) ? 5 : j - 1);
    const bool zmask = (j != 7);

    float part = (lane < 16) ? g_xsqp[b][lane] : 0.0f;
    float xoff = bfly_sum32(part) * NEG_INV;

    // t = 0 init (prior shift +10): state 0 is lane 0 / k 0.
    const float EXPM20 = 2.0611536e-09f;
    float4 w0a = *(const float4*)(rb + j * 8);
    float  w0e = rb[j * 8 + 4];
    float p0 = w0a.x * ((j == 0) ? 1.0f : EXPM20);
    float p1 = w0a.y * EXPM20;
    float p2 = w0a.z * EXPM20;
    float p3 = w0a.w * EXPM20;
    float p4 = w0e   * EXPM20;
    float Cacc = 10.0f;
    float zs = zmask ? (p0 + p1 + p2 + p3 + p4) : 0.0f;
    float S = bfly_sum8(zs);

    // ring prefetch depth 4: rows 1..4 in slots 0..3
    float4 wA[4], kA[4];
    float  wE[4], kE[4], Ws[4];
#pragma unroll
    for (int d = 0; d < 4; d++) {
        const float* r = rb + (size_t)(1 + d) * ROWW;
        wA[d] = *(const float4*)(r + j * 8);
        wE[d] = __ldg(r + j * 8 + 4);
        kA[d] = *(const float4*)(r + 64 + j * 8);
        kE[d] = __ldg(r + 64 + j * 8 + 4);
        Ws[d] = __ldg(wsb + 1 + d);
    }
    // R_1 = sum_i p_0,i * kappa_1,i   (kappa row 1 = slot 0)
    float z0 = fmaf(p0, kA[0].x, fmaf(p1, kA[0].y,
               fmaf(p2, kA[0].z, fmaf(p3, kA[0].w, p4 * kE[0]))));
    z0 = zmask ? z0 : 0.0f;
    float Rn = bfly_sum8(z0);

    const float* ldp = rb + (size_t)5 * ROWW;   // next row to load = t+4 (t starts 1)
    const float* ldw = wsb + 5;
    float rsave = 1.0f, lsave = 0.0f;
    for (int blk = 0; blk < 31; blk++) {        // t = 1..496
#pragma unroll
        for (int u16 = 0; u16 < 16; u16++) {
            int u  = u16 & 3;
            int un = (u16 + 1) & 3;             // slot holding row t+1 (kappa)
            fstep(p0, p1, p2, p3, p4, S, Rn,
                  wA[u], wE[u], kA[un], kE[un], Ws[u], jprev, zmask);
            wA[u] = *(const float4*)(ldp + j * 8);
            wE[u] = __ldg(ldp + j * 8 + 4);
            kA[u] = *(const float4*)(ldp + 64 + j * 8);
            kE[u] = __ldg(ldp + 64 + j * 8 + 4);
            Ws[u] = __ldg(ldw);
            ldp += ROWW;
            ldw += 1;
            if (u16 == 13) { rsave = __fdividef(1.0f, S); lsave = __logf(S); }
        }
        p0 *= rsave; p1 *= rsave; p2 *= rsave; p3 *= rsave; p4 *= rsave;
        S *= rsave; Rn *= rsave; Cacc += lsave;
    }
    // tail: t = 497..511 (refills read zero-padded rows; harmless)
#pragma unroll
    for (int u16 = 0; u16 < 15; u16++) {
        int u  = u16 & 3;
        int un = (u16 + 1) & 3;
        fstep(p0, p1, p2, p3, p4, S, Rn,
              wA[u], wE[u], kA[un], kE[un], Ws[u], jprev, zmask);
        wA[u] = *(const float4*)(ldp + j * 8);
        kA[u] = *(const float4*)(ldp + 64 + j * 8);
        wE[u] = __ldg(ldp + j * 8 + 4);
        kE[u] = __ldg(ldp + 64 + j * 8 + 4);
        Ws[u] = __ldg(ldw);
        ldp += ROWW;
        ldw += 1;
    }

    if (lane == 0) out[b] = __logf(S) + Cacc + xoff;
}

// ---------------------------------------------------------------------------
extern "C" void kernel_launch(void* const* d_in, const int* in_sizes, int n_in,
                              void* d_out, int out_size) {
    const float* obs = (const float*)d_in[0];  // [64,512,16,13,12]
    const float* m   = (const float*)d_in[1];  // [35,16,13,12]
    float* out = (float*)d_out;                // [64]

    k_gemm<<<BTROWS / 128, 128>>>(obs, m);     // 256 CTAs x 4 warps x 32 rows
    k_fwd<<<NB, 32>>>(out);
}

// round 9
// speedup vs baseline: 1.1840x; 1.1840x over previous
#include <cuda_runtime.h>
#include <cstdint>

#define NSTATES 35
#define NB      64
#define TT      512
#define DDIM    2496
#define BTROWS  (NB * TT)   // 32768
#define KC      64
#define NCH     39          // 2496/64
#define CPT     36          // columns per chunk (35 + 1 zero pad)
#define NCHK    16          // chunks per batch (32 steps each; last = 31)

// Scratch (no cudaMalloc)
__device__ float g_w[(size_t)BTROWS * 40];              // emission weights, 40-padded
__device__ float g_P[(size_t)NB * NCHK * CPT * 40];     // chunk product matrices, col-major
__device__ float g_xsqp[NB][16];                        // per-batch |x|^2 partials

// ---------------------------------------------------------------------------
// helpers
// ---------------------------------------------------------------------------
__device__ __forceinline__ uint32_t smem_u32(const void* p) {
    return (uint32_t)__cvta_generic_to_shared(p);
}
__device__ __forceinline__ uint32_t cvt_bf2(float lo, float hi) {
    uint32_t r;
    asm("cvt.rn.bf16x2.f32 %0, %1, %2;" : "=r"(r) : "f"(hi), "f"(lo));
    return r;
}
__device__ __forceinline__ void mma_bf16(float* d,
    uint32_t a0, uint32_t a1, uint32_t a2, uint32_t a3, uint32_t b0, uint32_t b1) {
    asm volatile(
        "mma.sync.aligned.m16n8k16.row.col.f32.bf16.bf16.f32 "
        "{%0,%1,%2,%3}, {%4,%5,%6,%7}, {%8,%9}, {%0,%1,%2,%3};\n"
        : "+f"(d[0]), "+f"(d[1]), "+f"(d[2]), "+f"(d[3])
        : "r"(a0), "r"(a1), "r"(a2), "r"(a3), "r"(b0), "r"(b1));
}
__device__ __forceinline__ void ldsm4(uint32_t* r, uint32_t a) {
    asm volatile("ldmatrix.sync.aligned.m8n8.x4.shared.b16 {%0,%1,%2,%3}, [%4];"
        : "=r"(r[0]), "=r"(r[1]), "=r"(r[2]), "=r"(r[3]) : "r"(a));
}
__device__ __forceinline__ void ldsm2(uint32_t* r, uint32_t a) {
    asm volatile("ldmatrix.sync.aligned.m8n8.x2.shared.b16 {%0,%1}, [%2];"
        : "=r"(r[0]), "=r"(r[1]) : "r"(a));
}
__device__ __forceinline__ void sts64(uint32_t addr, uint32_t a, uint32_t b) {
    asm volatile("st.shared.v2.b32 [%0], {%1,%2};" :: "r"(addr), "r"(a), "r"(b));
}
__device__ __forceinline__ float bfly_sum32(float v) {
    const unsigned FULL = 0xffffffffu;
    v += __shfl_xor_sync(FULL, v, 16);
    v += __shfl_xor_sync(FULL, v, 8);
    v += __shfl_xor_sync(FULL, v, 4);
    v += __shfl_xor_sync(FULL, v, 2);
    v += __shfl_xor_sync(FULL, v, 1);
    return v;
}

// ---------------------------------------------------------------------------
// GEMM: smem-staged bf16 m16n8k16 (proven core, at DRAM floor).
// Epilogue: w = exp((m_sq - 2*xm)/-500) into g_w[bt][40] (pads zero).
// ---------------------------------------------------------------------------
__global__ void __launch_bounds__(128) k_gemm(const float* __restrict__ x,
                                              const float* __restrict__ mM) {
    __shared__ __align__(16) unsigned char smraw[21504];  // A 16384 | B 5120
    __shared__ float msq[40];
    const int tid = threadIdx.x, wid = tid >> 5, lane = tid & 31;
    const int wstart = wid * 32;
    const int hhalf = lane >> 4;
    const int l4 = lane & 15;
    const int xl = lane & 7;
    const int rowBase = blockIdx.x * 128;
    const uint32_t smA = smem_u32(smraw);
    const uint32_t smB = smA + 16384;

    const uint32_t aAddr0 = smA + (uint32_t)(wstart + 0 * 16 + l4) * 128;
    const uint32_t aAddr1 = smA + (uint32_t)(wstart + 1 * 16 + l4) * 128;
    uint32_t bAddr[5];
#pragma unroll
    for (int nt = 0; nt < 5; nt++) bAddr[nt] = smB + (uint32_t)(nt * 8 + xl) * 128;
    const int hvA = hhalf;
    const int hvB = (lane >> 3) & 1;

    float acc[2][5][4];
#pragma unroll
    for (int mt = 0; mt < 2; mt++)
#pragma unroll
        for (int nt = 0; nt < 5; nt++)
#pragma unroll
            for (int i = 0; i < 4; i++) acc[mt][nt][i] = 0.f;

    float xa0 = 0.f, xa1 = 0.f, xa2 = 0.f, xa3 = 0.f;
    float bacc[5] = {0.f, 0.f, 0.f, 0.f, 0.f};
    float4 av[16], bvf[5];

#define LOADCHUNK(CH) do {                                                      \
    int kc0 = (CH) * KC;                                                        \
    _Pragma("unroll")                                                           \
    for (int i = 0; i < 16; i++) {                                              \
        int r = wstart + i * 2 + hhalf;                                         \
        av[i] = *(const float4*)(x + (size_t)(rowBase + r) * DDIM + kc0 + l4*4);\
    }                                                                           \
    _Pragma("unroll")                                                           \
    for (int k = 0; k < 5; k++) {                                               \
        int s = (wid + 4 * k) * 2 + hhalf;                                      \
        int ss = s < NSTATES ? s : NSTATES - 1;                                 \
        float4 t = *(const float4*)(mM + (size_t)ss * DDIM + kc0 + l4 * 4);     \
        if (s >= NSTATES) { t.x = 0.f; t.y = 0.f; t.z = 0.f; t.w = 0.f; }       \
        bvf[k] = t;                                                             \
    } } while (0)

#define CVTSTS() do {                                                           \
    _Pragma("unroll")                                                           \
    for (int i = 0; i < 16; i++) {                                              \
        int sr = wstart + i * 2 + hhalf;                                        \
        float4 v = av[i];                                                       \
        xa0 = fmaf(v.x, v.x, xa0); xa1 = fmaf(v.y, v.y, xa1);                   \
        xa2 = fmaf(v.z, v.z, xa2); xa3 = fmaf(v.w, v.w, xa3);                   \
        uint32_t lo = cvt_bf2(v.x, v.y), hi = cvt_bf2(v.z, v.w);                \
        uint32_t ad = smA + (uint32_t)sr * 128                                  \
                    + (uint32_t)((((l4 >> 1) ^ (sr & 7)) << 4) + ((l4 & 1) << 3)); \
        sts64(ad, lo, hi);                                                      \
    }                                                                           \
    _Pragma("unroll")                                                           \
    for (int k = 0; k < 5; k++) {                                               \
        int s = (wid + 4 * k) * 2 + hhalf;                                      \
        float4 v = bvf[k];                                                      \
        bacc[k] = fmaf(v.x, v.x, fmaf(v.y, v.y, fmaf(v.z, v.z,                  \
                  fmaf(v.w, v.w, bacc[k]))));                                   \
        uint32_t lo = cvt_bf2(v.x, v.y), hi = cvt_bf2(v.z, v.w);                \
        uint32_t ad = smB + (uint32_t)s * 128                                   \
                    + (uint32_t)((((l4 >> 1) ^ (s & 7)) << 4) + ((l4 & 1) << 3)); \
        sts64(ad, lo, hi);                                                      \
    } } while (0)

#define MMASEC() do {                                                           \
    _Pragma("unroll")                                                           \
    for (int kt = 0; kt < 4; kt++) {                                            \
        uint32_t A0[4], A1[4];                                                  \
        uint32_t offA = (uint32_t)(((kt * 2 + hvA) ^ xl) << 4);                 \
        ldsm4(A0, aAddr0 + offA);                                               \
        ldsm4(A1, aAddr1 + offA);                                               \
        uint32_t offB = (uint32_t)(((kt * 2 + hvB) ^ xl) << 4);                 \
        _Pragma("unroll")                                                       \
        for (int nt = 0; nt < 5; nt++) {                                        \
            uint32_t B[2];                                                      \
            ldsm2(B, bAddr[nt] + offB);                                         \
            mma_bf16(acc[0][nt], A0[0], A0[1], A0[2], A0[3], B[0], B[1]);       \
            mma_bf16(acc[1][nt], A1[0], A1[1], A1[2], A1[3], B[0], B[1]);       \
        }                                                                       \
    } } while (0)

    LOADCHUNK(0);
    CVTSTS();
    __syncthreads();

    for (int ch = 0; ch < NCH; ch++) {
        bool more = (ch + 1 < NCH);
        if (more) LOADCHUNK(ch + 1);
        MMASEC();
        __syncthreads();
        if (more) {
            CVTSTS();
            __syncthreads();
        }
    }

    // exact fp32 m_sq
#pragma unroll
    for (int k = 0; k < 5; k++) {
        float v = bacc[k];
        v += __shfl_xor_sync(0xffffffffu, v, 1);
        v += __shfl_xor_sync(0xffffffffu, v, 2);
        v += __shfl_xor_sync(0xffffffffu, v, 4);
        v += __shfl_xor_sync(0xffffffffu, v, 8);
        int s = (wid + 4 * k) * 2 + hhalf;
        if (l4 == 0) msq[s] = v;
    }
    __syncthreads();

    // direct epilogue: w stored to g_w[bt][40], pads zero
    const float NEG_INV = -1.0f / 500.0f;
    const int g = lane >> 2, c2 = lane & 3;
#pragma unroll
    for (int mt = 0; mt < 2; mt++) {
#pragma unroll
        for (int h = 0; h < 2; h++) {
            int row = rowBase + wstart + mt * 16 + g + h * 8;
#pragma unroll
            for (int nt = 0; nt < 5; nt++) {
                int col = nt * 8 + 2 * c2;
                float v0 = acc[mt][nt][2 * h + 0];
                float v1 = acc[mt][nt][2 * h + 1];
                float w0 = (col     < NSTATES) ? __expf((msq[col]     - 2.f * v0) * NEG_INV) : 0.f;
                float w1 = (col + 1 < NSTATES) ? __expf((msq[col + 1] - 2.f * v1) * NEG_INV) : 0.f;
                *(float2*)&g_w[(size_t)row * 40 + col] = make_float2(w0, w1);
            }
        }
    }

    float tot = bfly_sum32(xa0 + xa1 + xa2 + xa3);
    if (lane == 0)
        g_xsqp[(rowBase + wstart) >> 9][(blockIdx.x * 4 + wid) & 15] = tot;
}

// ---------------------------------------------------------------------------
// Phase 1: chunked scan. Thread = (chunk, column). Evolves one column of the
// chunk product matrix in registers: p'_j = w_j*(C1 p_j + C2 p_{j-1} +
// C3 p_{j-2} + EPS4*S), with (C1,C2,C3,EPS4) EXACTLY 4x the true transition
// constants (power-of-2 scale => exact). Effective chunk matrix = 4^nsteps *
// true matrix; total correction 511*ln4 subtracted once in k_comb.
// Column init 1.0. No shuffles, no syncs.
// ---------------------------------------------------------------------------
__global__ void __launch_bounds__(288) k_scan() {
    const int tid = threadIdx.x;
    const int cid = blockIdx.x * 8 + tid / CPT;   // 0..1023
    const int col = tid % CPT;                    // 0..35 (35 = zero column)
    const int b = cid >> 4, c = cid & 15;
    const int nsteps = (c == 15) ? 31 : 32;
    const float* wr = g_w + ((size_t)b * TT + 32 * c + 1) * 40;
    const float C1 = 0.1f  * 4.0f;
    const float C2 = 0.8f  * 4.0f;
    const float C3 = 0.08f * 4.0f;
    const float EPS4 = (0.02f / 35.0f) * 4.0f;

    float p[NSTATES];
#pragma unroll
    for (int i = 0; i < NSTATES; i++) p[i] = 0.f;
    float S = 0.f;
    if (col < NSTATES) { p[col] = 1.0f; S = 1.0f; }

#pragma unroll 1
    for (int s = 0; s < nsteps; s++) {
        float w_[36];
#pragma unroll
        for (int k = 0; k < 9; k++) {
            float4 t = __ldg((const float4*)wr + k);
            w_[4 * k] = t.x; w_[4 * k + 1] = t.y; w_[4 * k + 2] = t.z; w_[4 * k + 3] = t.w;
        }
        wr += 40;
        float sigma = EPS4 * S;
        float sv34 = p[34], sv33 = p[33];
#pragma unroll
        for (int j = 34; j >= 2; j--) {
            float t = fmaf(C2, p[j - 1], fmaf(C3, p[j - 2], sigma));
            t = fmaf(C1, p[j], t);
            p[j] = w_[j] * t;
        }
        {
            float t = fmaf(C2, p[0], fmaf(C3, sv34, sigma));
            t = fmaf(C1, p[1], t);
            p[1] = w_[1] * t;
        }
        {
            float t = fmaf(C2, sv34, fmaf(C3, sv33, sigma));
            t = fmaf(C1, p[0], t);
            p[0] = w_[0] * t;
        }
        float s0 = 0.f, s1 = 0.f, s2 = 0.f, s3 = 0.f;
#pragma unroll
        for (int j = 0; j < 32; j += 4) {
            s0 += p[j]; s1 += p[j + 1]; s2 += p[j + 2]; s3 += p[j + 3];
        }
        S = ((s0 + s1) + (s2 + s3)) + ((p[32] + p[33]) + p[34]);
    }

    // store column (40 floats, pads zero)
    float* dst = g_P + ((size_t)cid * CPT + col) * 40;
#pragma unroll
    for (int k = 0; k < 8; k++)
        *(float4*)(dst + 4 * k) = make_float4(p[4*k], p[4*k+1], p[4*k+2], p[4*k+3]);
    *(float4*)(dst + 32) = make_float4(p[32], p[33], p[34], 0.f);
    *(float4*)(dst + 36) = make_float4(0.f, 0.f, 0.f, 0.f);
}

// ---------------------------------------------------------------------------
// Phase 2: per-batch combine. 40 threads; thread i owns output row i.
// v <- P_c v with per-chunk renorm; out = Cacc + xoff - 511*ln4.
// ---------------------------------------------------------------------------
__global__ void k_comb(float* __restrict__ out) {
    __shared__ float vsh[40];
    __shared__ float ush[40];
    const int b = blockIdx.x;
    const int i = threadIdx.x;   // 0..39
    const float NEG_INV = -1.0f / 500.0f;
    const float LOGCORR = 708.39641853f;   // 511 * ln(4), exact scale accounting

    float xoff = 0.f;
#pragma unroll
    for (int k = 0; k < 16; k++) xoff += g_xsqp[b][k];
    xoff *= NEG_INV;

    // v init: alpha0 (prior shift +10): v[0] = w0[0], v[i] = w0[i]*e^-20
    const float EXPM20 = 2.0611536e-09f;
    float w0 = g_w[(size_t)b * TT * 40 + i];   // pads are 0
    vsh[i] = (i == 0) ? w0 : w0 * EXPM20;
    __syncthreads();

    float Cacc = 10.0f;
    for (int c = 0; c < NCHK; c++) {
        const float* Pc = g_P + (size_t)(b * NCHK + c) * CPT * 40;
        float acc = 0.f;
#pragma unroll 7
        for (int j = 0; j < NSTATES; j++)
            acc = fmaf(__ldg(Pc + j * 40 + i), vsh[j], acc);
        ush[i] = acc;
        __syncthreads();
        float Ssum = 0.f;
#pragma unroll
        for (int k = 0; k < 40; k += 4) {
            float4 t = *(const float4*)&ush[k];
            Ssum += (t.x + t.y) + (t.z + t.w);
        }
        float rs = __fdividef(1.0f, Ssum);
        Cacc += __logf(Ssum);
        vsh[i] = acc * rs;
        __syncthreads();
    }
    if (i == 0) out[b] = Cacc + xoff - LOGCORR;
}

// ---------------------------------------------------------------------------
extern "C" void kernel_launch(void* const* d_in, const int* in_sizes, int n_in,
                              void* d_out, int out_size) {
    const float* obs = (const float*)d_in[0];  // [64,512,16,13,12]
    const float* m   = (const float*)d_in[1];  // [35,16,13,12]
    float* out = (float*)d_out;                // [64]

    k_gemm<<<BTROWS / 128, 128>>>(obs, m);     // 256 CTAs
    k_scan<<<NB * NCHK / 8, 8 * CPT>>>();      // 128 CTAs x 288 thr
    k_comb<<<NB, 40>>>(out);
}

// round 10
// speedup vs baseline: 1.2348x; 1.0429x over previous
#include <cuda_runtime.h>
#include <cstdint>

#define NSTATES 35
#define NB      64
#define TT      512
#define DDIM    2496
#define BTROWS  (NB * TT)   // 32768
#define KC      64
#define NCH     39          // 2496/64
#define CPT     36          // columns per chunk (35 + 1 zero pad)
#define NCHK    16          // chunks per batch (32 steps each; last = 31)

// Scratch (no cudaMalloc). +1 pad row so scan's last prefetch stays in-bounds.
__device__ float g_w[(size_t)(BTROWS + 1) * 40];        // emission weights, 40-padded
__device__ float g_P[(size_t)NB * NCHK * CPT * 40];     // chunk product matrices
__device__ float g_xsqp[NB][16];                        // per-batch |x|^2 partials

// ---------------------------------------------------------------------------
// helpers
// ---------------------------------------------------------------------------
__device__ __forceinline__ uint32_t smem_u32(const void* p) {
    return (uint32_t)__cvta_generic_to_shared(p);
}
__device__ __forceinline__ uint32_t cvt_bf2(float lo, float hi) {
    uint32_t r;
    asm("cvt.rn.bf16x2.f32 %0, %1, %2;" : "=r"(r) : "f"(hi), "f"(lo));
    return r;
}
__device__ __forceinline__ void mma_bf16(float* d,
    uint32_t a0, uint32_t a1, uint32_t a2, uint32_t a3, uint32_t b0, uint32_t b1) {
    asm volatile(
        "mma.sync.aligned.m16n8k16.row.col.f32.bf16.bf16.f32 "
        "{%0,%1,%2,%3}, {%4,%5,%6,%7}, {%8,%9}, {%0,%1,%2,%3};\n"
        : "+f"(d[0]), "+f"(d[1]), "+f"(d[2]), "+f"(d[3])
        : "r"(a0), "r"(a1), "r"(a2), "r"(a3), "r"(b0), "r"(b1));
}
__device__ __forceinline__ void ldsm4(uint32_t* r, uint32_t a) {
    asm volatile("ldmatrix.sync.aligned.m8n8.x4.shared.b16 {%0,%1,%2,%3}, [%4];"
        : "=r"(r[0]), "=r"(r[1]), "=r"(r[2]), "=r"(r[3]) : "r"(a));
}
__device__ __forceinline__ void ldsm2(uint32_t* r, uint32_t a) {
    asm volatile("ldmatrix.sync.aligned.m8n8.x2.shared.b16 {%0,%1}, [%2];"
        : "=r"(r[0]), "=r"(r[1]) : "r"(a));
}
__device__ __forceinline__ void sts64(uint32_t addr, uint32_t a, uint32_t b) {
    asm volatile("st.shared.v2.b32 [%0], {%1,%2};" :: "r"(addr), "r"(a), "r"(b));
}
__device__ __forceinline__ float bfly_sum32(float v) {
    const unsigned FULL = 0xffffffffu;
    v += __shfl_xor_sync(FULL, v, 16);
    v += __shfl_xor_sync(FULL, v, 8);
    v += __shfl_xor_sync(FULL, v, 4);
    v += __shfl_xor_sync(FULL, v, 2);
    v += __shfl_xor_sync(FULL, v, 1);
    return v;
}

// ---------------------------------------------------------------------------
// GEMM: smem-staged bf16 m16n8k16, DOUBLE-BUFFERED smem, one sync per chunk.
// Epilogue: w = exp((m_sq - 2*xm)/-500) into g_w[bt][40] (pads zero).
// ---------------------------------------------------------------------------
__global__ void __launch_bounds__(128) k_gemm(const float* __restrict__ x,
                                              const float* __restrict__ mM) {
    // A0 @0 (16K) | A1 @16384 | B0 @32768 (5K) | B1 @37888 ; total 43008
    __shared__ __align__(16) unsigned char smraw[43008];
    __shared__ float msq[40];
    const int tid = threadIdx.x, wid = tid >> 5, lane = tid & 31;
    const int wstart = wid * 32;
    const int hhalf = lane >> 4;
    const int l4 = lane & 15;
    const int xl = lane & 7;
    const int rowBase = blockIdx.x * 128;
    const uint32_t smA = smem_u32(smraw);
    const uint32_t smB = smA + 32768;

    const uint32_t aAddr0 = smA + (uint32_t)(wstart + 0 * 16 + l4) * 128;
    const uint32_t aAddr1 = smA + (uint32_t)(wstart + 1 * 16 + l4) * 128;
    uint32_t bAddr[5];
#pragma unroll
    for (int nt = 0; nt < 5; nt++) bAddr[nt] = smB + (uint32_t)(nt * 8 + xl) * 128;
    const int hvA = hhalf;
    const int hvB = (lane >> 3) & 1;

    float acc[2][5][4];
#pragma unroll
    for (int mt = 0; mt < 2; mt++)
#pragma unroll
        for (int nt = 0; nt < 5; nt++)
#pragma unroll
            for (int i = 0; i < 4; i++) acc[mt][nt][i] = 0.f;

    float xa0 = 0.f, xa1 = 0.f, xa2 = 0.f, xa3 = 0.f;
    float bacc[5] = {0.f, 0.f, 0.f, 0.f, 0.f};
    float4 av[16], bvf[5];

#define LOADCHUNK(CH) do {                                                      \
    int kc0 = (CH) * KC;                                                        \
    _Pragma("unroll")                                                           \
    for (int i = 0; i < 16; i++) {                                              \
        int r = wstart + i * 2 + hhalf;                                         \
        av[i] = *(const float4*)(x + (size_t)(rowBase + r) * DDIM + kc0 + l4*4);\
    }                                                                           \
    _Pragma("unroll")                                                           \
    for (int k = 0; k < 5; k++) {                                               \
        int s = (wid + 4 * k) * 2 + hhalf;                                      \
        int ss = s < NSTATES ? s : NSTATES - 1;                                 \
        float4 t = *(const float4*)(mM + (size_t)ss * DDIM + kc0 + l4 * 4);     \
        if (s >= NSTATES) { t.x = 0.f; t.y = 0.f; t.z = 0.f; t.w = 0.f; }       \
        bvf[k] = t;                                                             \
    } } while (0)

#define CVTSTS(AOFF, BOFF) do {                                                 \
    _Pragma("unroll")                                                           \
    for (int i = 0; i < 16; i++) {                                              \
        int sr = wstart + i * 2 + hhalf;                                        \
        float4 v = av[i];                                                       \
        xa0 = fmaf(v.x, v.x, xa0); xa1 = fmaf(v.y, v.y, xa1);                   \
        xa2 = fmaf(v.z, v.z, xa2); xa3 = fmaf(v.w, v.w, xa3);                   \
        uint32_t lo = cvt_bf2(v.x, v.y), hi = cvt_bf2(v.z, v.w);                \
        uint32_t ad = smA + (AOFF) + (uint32_t)sr * 128                         \
                    + (uint32_t)((((l4 >> 1) ^ (sr & 7)) << 4) + ((l4 & 1) << 3)); \
        sts64(ad, lo, hi);                                                      \
    }                                                                           \
    _Pragma("unroll")                                                           \
    for (int k = 0; k < 5; k++) {                                               \
        int s = (wid + 4 * k) * 2 + hhalf;                                      \
        float4 v = bvf[k];                                                      \
        bacc[k] = fmaf(v.x, v.x, fmaf(v.y, v.y, fmaf(v.z, v.z,                  \
                  fmaf(v.w, v.w, bacc[k]))));                                   \
        uint32_t lo = cvt_bf2(v.x, v.y), hi = cvt_bf2(v.z, v.w);                \
        uint32_t ad = smB + (BOFF) + (uint32_t)s * 128                          \
                    + (uint32_t)((((l4 >> 1) ^ (s & 7)) << 4) + ((l4 & 1) << 3)); \
        sts64(ad, lo, hi);                                                      \
    } } while (0)

#define MMASEC(AOFF, BOFF) do {                                                 \
    _Pragma("unroll")                                                           \
    for (int kt = 0; kt < 4; kt++) {                                            \
        uint32_t A0[4], A1[4];                                                  \
        uint32_t offA = (AOFF) + (uint32_t)(((kt * 2 + hvA) ^ xl) << 4);        \
        ldsm4(A0, aAddr0 + offA);                                               \
        ldsm4(A1, aAddr1 + offA);                                               \
        uint32_t offB = (BOFF) + (uint32_t)(((kt * 2 + hvB) ^ xl) << 4);        \
        _Pragma("unroll")                                                       \
        for (int nt = 0; nt < 5; nt++) {                                        \
            uint32_t B[2];                                                      \
            ldsm2(B, bAddr[nt] + offB);                                         \
            mma_bf16(acc[0][nt], A0[0], A0[1], A0[2], A0[3], B[0], B[1]);       \
            mma_bf16(acc[1][nt], A1[0], A1[1], A1[2], A1[3], B[0], B[1]);       \
        }                                                                       \
    } } while (0)

    LOADCHUNK(0);
    CVTSTS(0u, 0u);
    __syncthreads();

#pragma unroll 2
    for (int ch = 0; ch < NCH; ch++) {
        uint32_t aCur = (ch & 1) ? 16384u : 0u;
        uint32_t bCur = (ch & 1) ? 5120u : 0u;
        uint32_t aNxt = (ch & 1) ? 0u : 16384u;
        uint32_t bNxt = (ch & 1) ? 0u : 5120u;
        bool more = (ch + 1 < NCH);
        if (more) LOADCHUNK(ch + 1);
        MMASEC(aCur, bCur);
        if (more) CVTSTS(aNxt, bNxt);
        __syncthreads();
    }

    // exact fp32 m_sq
#pragma unroll
    for (int k = 0; k < 5; k++) {
        float v = bacc[k];
        v += __shfl_xor_sync(0xffffffffu, v, 1);
        v += __shfl_xor_sync(0xffffffffu, v, 2);
        v += __shfl_xor_sync(0xffffffffu, v, 4);
        v += __shfl_xor_sync(0xffffffffu, v, 8);
        int s = (wid + 4 * k) * 2 + hhalf;
        if (l4 == 0) msq[s] = v;
    }
    __syncthreads();

    // direct epilogue: w stored to g_w[bt][40], pads zero
    const float NEG_INV = -1.0f / 500.0f;
    const int g = lane >> 2, c2 = lane & 3;
#pragma unroll
    for (int mt = 0; mt < 2; mt++) {
#pragma unroll
        for (int h = 0; h < 2; h++) {
            int row = rowBase + wstart + mt * 16 + g + h * 8;
#pragma unroll
            for (int nt = 0; nt < 5; nt++) {
                int col = nt * 8 + 2 * c2;
                float v0 = acc[mt][nt][2 * h + 0];
                float v1 = acc[mt][nt][2 * h + 1];
                float w0 = (col     < NSTATES) ? __expf((msq[col]     - 2.f * v0) * NEG_INV) : 0.f;
                float w1 = (col + 1 < NSTATES) ? __expf((msq[col + 1] - 2.f * v1) * NEG_INV) : 0.f;
                *(float2*)&g_w[(size_t)row * 40 + col] = make_float2(w0, w1);
            }
        }
    }

    float tot = bfly_sum32(xa0 + xa1 + xa2 + xa3);
    if (lane == 0)
        g_xsqp[(rowBase + wstart) >> 9][(blockIdx.x * 4 + wid) & 15] = tot;
}

// ---------------------------------------------------------------------------
// Phase 1: chunked scan with SOFTWARE-PIPELINED w-row prefetch. Thread =
// (chunk, column); evolves one column of the chunk product matrix in
// registers with constants EXACTLY 4x the true values (power-of-2 scale).
// Correction 511*ln4 subtracted once in k_comb. No shuffles, no syncs.
// ---------------------------------------------------------------------------
__global__ void __launch_bounds__(288) k_scan() {
    const int tid = threadIdx.x;
    const int cid = blockIdx.x * 8 + tid / CPT;   // 0..1023
    const int col = tid % CPT;                    // 0..35 (35 = zero column)
    const int b = cid >> 4, c = cid & 15;
    const int nsteps = (c == 15) ? 31 : 32;
    const float* wr = g_w + ((size_t)b * TT + 32 * c + 1) * 40;
    const float C1 = 0.1f  * 4.0f;
    const float C2 = 0.8f  * 4.0f;
    const float C3 = 0.08f * 4.0f;
    const float EPS4 = (0.02f / 35.0f) * 4.0f;

    float p[NSTATES];
#pragma unroll
    for (int i = 0; i < NSTATES; i++) p[i] = 0.f;
    float S = 0.f;
    if (col < NSTATES) { p[col] = 1.0f; S = 1.0f; }

    // prefetch row for step 0
    float4 wv[9];
#pragma unroll
    for (int k = 0; k < 9; k++) wv[k] = __ldg((const float4*)wr + k);

#pragma unroll 1
    for (int s = 0; s < nsteps; s++) {
        // consume current row into scalars, then immediately prefetch next
        float w_[36];
#pragma unroll
        for (int k = 0; k < 9; k++) {
            w_[4 * k] = wv[k].x; w_[4 * k + 1] = wv[k].y;
            w_[4 * k + 2] = wv[k].z; w_[4 * k + 3] = wv[k].w;
        }
        wr += 40;
#pragma unroll
        for (int k = 0; k < 9; k++) wv[k] = __ldg((const float4*)wr + k);

        float sigma = EPS4 * S;
        float sv34 = p[34], sv33 = p[33];
#pragma unroll
        for (int j = 34; j >= 2; j--) {
            float t = fmaf(C2, p[j - 1], fmaf(C3, p[j - 2], sigma));
            t = fmaf(C1, p[j], t);
            p[j] = w_[j] * t;
        }
        {
            float t = fmaf(C2, p[0], fmaf(C3, sv34, sigma));
            t = fmaf(C1, p[1], t);
            p[1] = w_[1] * t;
        }
        {
            float t = fmaf(C2, sv34, fmaf(C3, sv33, sigma));
            t = fmaf(C1, p[0], t);
            p[0] = w_[0] * t;
        }
        float s0 = 0.f, s1 = 0.f, s2 = 0.f, s3 = 0.f;
#pragma unroll
        for (int j = 0; j < 32; j += 4) {
            s0 += p[j]; s1 += p[j + 1]; s2 += p[j + 2]; s3 += p[j + 3];
        }
        S = ((s0 + s1) + (s2 + s3)) + ((p[32] + p[33]) + p[34]);
    }

    // store column (40 floats, pads zero)
    float* dst = g_P + ((size_t)cid * CPT + col) * 40;
#pragma unroll
    for (int k = 0; k < 8; k++)
        *(float4*)(dst + 4 * k) = make_float4(p[4*k], p[4*k+1], p[4*k+2], p[4*k+3]);
    *(float4*)(dst + 32) = make_float4(p[32], p[33], p[34], 0.f);
    *(float4*)(dst + 36) = make_float4(0.f, 0.f, 0.f, 0.f);
}

// ---------------------------------------------------------------------------
// Phase 2: per-batch combine. 40 threads; thread i owns output row i.
// v <- P_c v with per-chunk renorm; out = Cacc + xoff - 511*ln4.
// ---------------------------------------------------------------------------
__global__ void k_comb(float* __restrict__ out) {
    __shared__ float vsh[40];
    __shared__ float ush[40];
    const int b = blockIdx.x;
    const int i = threadIdx.x;   // 0..39
    const float NEG_INV = -1.0f / 500.0f;
    const float LOGCORR = 708.39641853f;   // 511 * ln(4), exact scale accounting

    float xoff = 0.f;
#pragma unroll
    for (int k = 0; k < 16; k++) xoff += g_xsqp[b][k];
    xoff *= NEG_INV;

    // v init: alpha0 (prior shift +10): v[0] = w0[0], v[i] = w0[i]*e^-20
    const float EXPM20 = 2.0611536e-09f;
    float w0 = g_w[(size_t)b * TT * 40 + i];   // pads are 0
    vsh[i] = (i == 0) ? w0 : w0 * EXPM20;
    __syncthreads();

    float Cacc = 10.0f;
    for (int c = 0; c < NCHK; c++) {
        const float* Pc = g_P + (size_t)(b * NCHK + c) * CPT * 40;
        float acc = 0.f;
#pragma unroll 7
        for (int j = 0; j < NSTATES; j++)
            acc = fmaf(__ldg(Pc + j * 40 + i), vsh[j], acc);
        ush[i] = acc;
        __syncthreads();
        float Ssum = 0.f;
#pragma unroll
        for (int k = 0; k < 40; k += 4) {
            float4 t = *(const float4*)&ush[k];
            Ssum += (t.x + t.y) + (t.z + t.w);
        }
        float rs = __fdividef(1.0f, Ssum);
        Cacc += __logf(Ssum);
        vsh[i] = acc * rs;
        __syncthreads();
    }
    if (i == 0) out[b] = Cacc + xoff - LOGCORR;
}

// ---------------------------------------------------------------------------
extern "C" void kernel_launch(void* const* d_in, const int* in_sizes, int n_in,
                              void* d_out, int out_size) {
    const float* obs = (const float*)d_in[0];  // [64,512,16,13,12]
    const float* m   = (const float*)d_in[1];  // [35,16,13,12]
    float* out = (float*)d_out;                // [64]

    k_gemm<<<BTROWS / 128, 128>>>(obs, m);     // 256 CTAs
    k_scan<<<NB * NCHK / 8, 8 * CPT>>>();      // 128 CTAs x 288 thr
    k_comb<<<NB, 40>>>(out);
}